// round 13
// baseline (speedup 1.0000x reference)
#include <cuda_runtime.h>
#include <cuda_bf16.h>
#include <cstdint>

// ContactMapHead — SINGLE persistent kernel (launch overhead ~4us/launch was
// ~12us of the 49.6us total). Phases separated by software grid barriers:
//   P0: proj_w fp32 -> g_w bf16            (cvt, 1/256 per CTA)
//   P1: h = relu(X @ W^T + b) -> g_h       (R5-proven body, tile=(bid&1,bid>>1))
//   P2: out = (h h^T)*w + c, triangle      (R9-proven body, persistent tiles)
// Grid 256 CTAs, occ 2 (<=296 slots) => all resident => barriers deadlock-free.

__device__ __nv_bfloat16 g_h[4 * 2048 * 256];
__device__ __nv_bfloat16 g_w[256 * 1024];
__device__ unsigned long long g_arrive = 0;  // cumulative arrivals (monotone, no reset)

static __device__ __forceinline__ uint32_t smem_u32(const void* p) {
    return (uint32_t)__cvta_generic_to_shared(p);
}
static __device__ __forceinline__ void ldsm_x4(unsigned r[4], uint32_t a) {
    asm volatile("ldmatrix.sync.aligned.m8n8.x4.shared.b16 {%0,%1,%2,%3}, [%4];"
                 : "=r"(r[0]), "=r"(r[1]), "=r"(r[2]), "=r"(r[3]) : "r"(a));
}
static __device__ __forceinline__ void mma16816(float c[4], const unsigned a[4], const unsigned b[2]) {
    asm volatile("mma.sync.aligned.m16n8k16.row.col.f32.bf16.bf16.f32 "
                 "{%0,%1,%2,%3}, {%4,%5,%6,%7}, {%8,%9}, {%0,%1,%2,%3};"
                 : "+f"(c[0]), "+f"(c[1]), "+f"(c[2]), "+f"(c[3])
                 : "r"(a[0]), "r"(a[1]), "r"(a[2]), "r"(a[3]), "r"(b[0]), "r"(b[1]));
}
static __device__ __forceinline__ unsigned packbf(float a, float b) {
    __nv_bfloat162 t = __floats2bfloat162_rn(a, b);
    return *reinterpret_cast<unsigned*>(&t);
}
static __device__ __forceinline__ void cp16(uint32_t saddr, const void* gptr) {
    asm volatile("cp.async.cg.shared.global [%0], [%1], 16;" :: "r"(saddr), "l"(gptr) : "memory");
}
static __device__ __forceinline__ void cp_commit() {
    asm volatile("cp.async.commit_group;" ::: "memory");
}
static __device__ __forceinline__ void cp_wait1() {
    asm volatile("cp.async.wait_group 1;" ::: "memory");
}
static __device__ __forceinline__ void cp_wait0() {
    asm volatile("cp.async.wait_group 0;" ::: "memory");
}

#define NT 256
#define NCTAS 256

// Sense-free grid barrier: cumulative arrival count; works across launches and
// ncu replays (target derived from own ticket). Requires all CTAs resident.
static __device__ __forceinline__ void grid_barrier() {
    __syncthreads();
    __threadfence();
    if (threadIdx.x == 0) {
        unsigned long long old = atomicAdd(&g_arrive, 1ULL);
        unsigned long long target = (old / NCTAS + 1) * (unsigned long long)NCTAS;
        while (*((volatile unsigned long long*)&g_arrive) < target) {}
    }
    __syncthreads();
    __threadfence();
}

__global__ __launch_bounds__(NT, 2) void fused_head(const float* __restrict__ X,
                                                    const float* __restrict__ W,
                                                    const float* __restrict__ bias,
                                                    const float* __restrict__ clfw,
                                                    const float* __restrict__ clfb,
                                                    float* __restrict__ out) {
    extern __shared__ __align__(16) char smem[];
    const uint32_t sb = smem_u32(smem);
    const int tid = threadIdx.x;
    const int warp = tid >> 5, lane = tid & 31;
    const int bid = blockIdx.x;  // 0..255

    // ---------------- Phase 0: cvt W (each CTA converts 1024 floats) --------
    {
        int i = bid * NT + tid;  // 65536 threads x 4 elems
        float4 v = *(const float4*)(W + (size_t)i * 4);
        uint2 u;
        u.x = packbf(v.x, v.y);
        u.y = packbf(v.z, v.w);
        *(uint2*)(g_w + (size_t)i * 4) = u;
    }
    grid_barrier();

    // ---------------- Phase 1: proj (R5 body; tile = (bid&1, bid>>1)) ------
    {
        const int wm = (warp >> 2) * 32;
        const int wn = (warp & 3) * 32;
        const int mBase = (bid >> 1) * 64;
        const int nBase = (bid & 1) * 128;

        float4 rA[4];
        auto ldgA = [&](int kt) {
#pragma unroll
            for (int i = 0; i < 2; i++) {
                int c = tid + i * NT;
                int row = c >> 3, ch = c & 7;
                const float4* p =
                    (const float4*)(X + (size_t)(mBase + row) * 1024 + kt * 64 + ch * 8);
                rA[2 * i] = p[0];
                rA[2 * i + 1] = p[1];
            }
        };
        auto stsA = [&](int buf) {
            char* s = smem + buf * 24576;
#pragma unroll
            for (int i = 0; i < 2; i++) {
                int c = tid + i * NT;
                int row = c >> 3, ch = c & 7;
                uint4 u;
                u.x = packbf(rA[2 * i].x, rA[2 * i].y);
                u.y = packbf(rA[2 * i].z, rA[2 * i].w);
                u.z = packbf(rA[2 * i + 1].x, rA[2 * i + 1].y);
                u.w = packbf(rA[2 * i + 1].z, rA[2 * i + 1].w);
                *(uint4*)(s + row * 128 + ((ch ^ (row & 7)) << 4)) = u;
            }
        };
        auto issueB = [&](int kt, int buf) {
            const uint32_t B0 = sb + buf * 24576 + 8192;
#pragma unroll
            for (int i = 0; i < 4; i++) {
                int c = tid + i * NT;
                int row = c >> 3, ch = c & 7;
                cp16(B0 + row * 128 + ((ch ^ (row & 7)) << 4),
                     g_w + (size_t)(nBase + row) * 1024 + kt * 64 + ch * 8);
            }
            cp_commit();
        };

        float acc[2][4][4];
#pragma unroll
        for (int mi = 0; mi < 2; mi++)
#pragma unroll
            for (int ni = 0; ni < 4; ni++)
#pragma unroll
                for (int j = 0; j < 4; j++) acc[mi][ni][j] = 0.f;

        ldgA(0);
        stsA(0);
        issueB(0, 0);
        ldgA(1);

        for (int kt = 0; kt < 16; kt++) {
            cp_wait0();
            __syncthreads();
            if (kt + 1 < 16) issueB(kt + 1, (kt + 1) & 1);
            const uint32_t aB = sb + (kt & 1) * 24576, bB = aB + 8192;
#pragma unroll
            for (int ks = 0; ks < 4; ks++) {
                unsigned af[2][4], bfr[4][2];
#pragma unroll
                for (int mi = 0; mi < 2; mi++) {
                    int row = wm + mi * 16 + (lane & 15);
                    int kch = ks * 2 + (lane >> 4);
                    ldsm_x4(af[mi], aB + row * 128 + ((kch ^ (row & 7)) << 4));
                }
#pragma unroll
                for (int h = 0; h < 2; h++) {
                    unsigned q[4];
                    int nr = wn + h * 16 + (lane & 7) + ((lane >> 4) << 3);
                    int kch = ks * 2 + ((lane >> 3) & 1);
                    ldsm_x4(q, bB + nr * 128 + ((kch ^ (nr & 7)) << 4));
                    bfr[2 * h][0] = q[0]; bfr[2 * h][1] = q[1];
                    bfr[2 * h + 1][0] = q[2]; bfr[2 * h + 1][1] = q[3];
                }
#pragma unroll
                for (int mi = 0; mi < 2; mi++)
#pragma unroll
                    for (int ni = 0; ni < 4; ni++) mma16816(acc[mi][ni], af[mi], bfr[ni]);
            }
            if (kt + 1 < 16) {
                stsA((kt + 1) & 1);
                if (kt + 2 < 16) ldgA(kt + 2);
            }
        }

#pragma unroll
        for (int mi = 0; mi < 2; mi++) {
            int r = mBase + wm + mi * 16 + (lane >> 2);
#pragma unroll
            for (int ni = 0; ni < 4; ni++) {
                int cidx = nBase + wn + ni * 8 + ((lane & 3) << 1);
                float b0 = bias[cidx], b1 = bias[cidx + 1];
                float v00 = fmaxf(acc[mi][ni][0] + b0, 0.f);
                float v01 = fmaxf(acc[mi][ni][1] + b1, 0.f);
                float v10 = fmaxf(acc[mi][ni][2] + b0, 0.f);
                float v11 = fmaxf(acc[mi][ni][3] + b1, 0.f);
                *(__nv_bfloat162*)&g_h[(size_t)r * 256 + cidx] = __floats2bfloat162_rn(v00, v01);
                *(__nv_bfloat162*)&g_h[(size_t)(r + 8) * 256 + cidx] =
                    __floats2bfloat162_rn(v10, v11);
            }
        }
    }
    grid_barrier();

    // ---------------- Phase 2: gram (R9 body; persistent over 544 tiles) ----
    const float w = clfw[0], cb = clfb[0];
    for (int tile = bid; tile < 544; tile += NCTAS) {
        const int b = tile / 136;
        int t = tile - b * 136, ti = 0;
        while (t >= 16 - ti) { t -= 16 - ti; ti++; }
        const int tj = ti + t;
        const int wm = (warp >> 2) * 64;
        const int wn = (warp & 3) * 32;
        const int mBase = ti * 128, nBase = tj * 128;
        const __nv_bfloat16* hb = g_h + (size_t)b * (2048 * 256);

        auto issue = [&](int kt, int buf) {
            const uint32_t A0 = sb + buf * 32768, B0 = A0 + 16384;
#pragma unroll
            for (int i = 0; i < 4; i++) {
                int c = tid + i * NT;
                int r = c >> 3, ch = c & 7;
                uint32_t dst = (uint32_t)(r * 128 + ((ch ^ (r & 7)) << 4));
                cp16(A0 + dst, hb + (size_t)(mBase + r) * 256 + kt * 64 + ch * 8);
                cp16(B0 + dst, hb + (size_t)(nBase + r) * 256 + kt * 64 + ch * 8);
            }
            cp_commit();
        };

        float acc[4][4][4];
#pragma unroll
        for (int mi = 0; mi < 4; mi++)
#pragma unroll
            for (int ni = 0; ni < 4; ni++)
#pragma unroll
                for (int j = 0; j < 4; j++) acc[mi][ni][j] = 0.f;

        issue(0, 0);
        issue(1, 1);

        for (int kt = 0; kt < 4; kt++) {
            if (kt < 3) cp_wait1(); else cp_wait0();
            __syncthreads();
            if (kt + 2 < 4) issue(kt + 2, (kt + 2) % 3);
            const uint32_t aB = sb + (kt % 3) * 32768, bB = aB + 16384;
#pragma unroll
            for (int ks = 0; ks < 4; ks++) {
                unsigned af[4][4], bfr[4][2];
#pragma unroll
                for (int mi = 0; mi < 4; mi++) {
                    int row = wm + mi * 16 + (lane & 15);
                    int kch = ks * 2 + (lane >> 4);
                    ldsm_x4(af[mi], aB + row * 128 + ((kch ^ (row & 7)) << 4));
                }
#pragma unroll
                for (int h = 0; h < 2; h++) {
                    unsigned q[4];
                    int nr = wn + h * 16 + (lane & 7) + ((lane >> 4) << 3);
                    int kch = ks * 2 + ((lane >> 3) & 1);
                    ldsm_x4(q, bB + nr * 128 + ((kch ^ (nr & 7)) << 4));
                    bfr[2 * h][0] = q[0]; bfr[2 * h][1] = q[1];
                    bfr[2 * h + 1][0] = q[2]; bfr[2 * h + 1][1] = q[3];
                }
#pragma unroll
                for (int mi = 0; mi < 4; mi++)
#pragma unroll
                    for (int ni = 0; ni < 4; ni++) mma16816(acc[mi][ni], af[mi], bfr[ni]);
            }
        }
        __syncthreads();  // done reading pipeline smem

        float* op = out + (size_t)b * 2048 * 2048;
        float* ct = (float*)smem;

#pragma unroll
        for (int mi = 0; mi < 4; mi++) {
            int lr = wm + mi * 16 + (lane >> 2);
#pragma unroll
            for (int ni = 0; ni < 4; ni++) {
                int lc = wn + ni * 8 + ((lane & 3) << 1);
                float v00 = fmaf(acc[mi][ni][0], w, cb);
                float v01 = fmaf(acc[mi][ni][1], w, cb);
                float v10 = fmaf(acc[mi][ni][2], w, cb);
                float v11 = fmaf(acc[mi][ni][3], w, cb);
                *(float2*)&op[(size_t)(mBase + lr) * 2048 + nBase + lc] = make_float2(v00, v01);
                *(float2*)&op[(size_t)(mBase + lr + 8) * 2048 + nBase + lc] =
                    make_float2(v10, v11);
                if (ti != tj) {
                    ct[lc * 132 + lr] = v00;
                    ct[(lc + 1) * 132 + lr] = v01;
                    ct[lc * 132 + lr + 8] = v10;
                    ct[(lc + 1) * 132 + lr + 8] = v11;
                }
            }
        }
        if (ti != tj) {
            __syncthreads();
#pragma unroll
            for (int idx = tid; idx < 4096; idx += NT) {
                int rr = idx >> 5, cc = idx & 31;
                float4 v = *(float4*)&ct[rr * 132 + cc * 4];
                *(float4*)&op[(size_t)(nBase + rr) * 2048 + mBase + cc * 4] = v;
            }
        }
        __syncthreads();  // ct / stage smem free for next tile
    }
}

extern "C" void kernel_launch(void* const* d_in, const int* in_sizes, int n_in,
                              void* d_out, int out_size) {
    (void)in_sizes; (void)n_in; (void)out_size;
    const float* hidden = (const float*)d_in[0];  // [4,2048,1024]
    const float* proj_w = (const float*)d_in[1];  // [256,1024]
    const float* proj_b = (const float*)d_in[2];  // [256]
    const float* clf_w = (const float*)d_in[3];   // [1,1]
    const float* clf_b = (const float*)d_in[4];   // [1]
    float* out = (float*)d_out;                   // [4,2048,2048]

    cudaFuncSetAttribute(fused_head, cudaFuncAttributeMaxDynamicSharedMemorySize, 98304);
    fused_head<<<NCTAS, NT, 98304>>>(hidden, proj_w, proj_b, clf_w, clf_b, out);
}

// round 14
// speedup vs baseline: 1.1161x; 1.1161x over previous
#include <cuda_runtime.h>
#include <cuda_bf16.h>
#include <cstdint>

// ContactMapHead, mma.sync path. R9 schedule (3 launches).
//   cvt_w:    byte-identical to R9
//   proj_mma: ONLY change vs R9: B triple-buffered + cp_wait1 (each B stage
//             gets ~2 mainloop bodies of latency budget instead of ~1).
//   gram_mma: byte-identical to R9.

__device__ __nv_bfloat16 g_h[4 * 2048 * 256];
__device__ __nv_bfloat16 g_w[256 * 1024];

static __device__ __forceinline__ uint32_t smem_u32(const void* p) {
    return (uint32_t)__cvta_generic_to_shared(p);
}
static __device__ __forceinline__ void ldsm_x4(unsigned r[4], uint32_t a) {
    asm volatile("ldmatrix.sync.aligned.m8n8.x4.shared.b16 {%0,%1,%2,%3}, [%4];"
                 : "=r"(r[0]), "=r"(r[1]), "=r"(r[2]), "=r"(r[3]) : "r"(a));
}
static __device__ __forceinline__ void mma16816(float c[4], const unsigned a[4], const unsigned b[2]) {
    asm volatile("mma.sync.aligned.m16n8k16.row.col.f32.bf16.bf16.f32 "
                 "{%0,%1,%2,%3}, {%4,%5,%6,%7}, {%8,%9}, {%0,%1,%2,%3};"
                 : "+f"(c[0]), "+f"(c[1]), "+f"(c[2]), "+f"(c[3])
                 : "r"(a[0]), "r"(a[1]), "r"(a[2]), "r"(a[3]), "r"(b[0]), "r"(b[1]));
}
static __device__ __forceinline__ unsigned packbf(float a, float b) {
    __nv_bfloat162 t = __floats2bfloat162_rn(a, b);
    return *reinterpret_cast<unsigned*>(&t);
}
static __device__ __forceinline__ void cp16(uint32_t saddr, const void* gptr) {
    asm volatile("cp.async.cg.shared.global [%0], [%1], 16;" :: "r"(saddr), "l"(gptr) : "memory");
}
static __device__ __forceinline__ void cp_commit() {
    asm volatile("cp.async.commit_group;" ::: "memory");
}
static __device__ __forceinline__ void cp_wait1() {
    asm volatile("cp.async.wait_group 1;" ::: "memory");
}
static __device__ __forceinline__ void cp_wait0() {
    asm volatile("cp.async.wait_group 0;" ::: "memory");
}

#define NT 256

// ================= cvt_w: proj_w fp32 -> bf16 (byte-identical R9) ====
__global__ void cvt_w(const float* __restrict__ W) {
    int i = blockIdx.x * blockDim.x + threadIdx.x;  // 32768 threads x 8 elems
    const float4* p = (const float4*)(W + (size_t)i * 8);
    float4 v0 = p[0], v1 = p[1];
    uint4 u;
    u.x = packbf(v0.x, v0.y); u.y = packbf(v0.z, v0.w);
    u.z = packbf(v1.x, v1.y); u.w = packbf(v1.z, v1.w);
    *(uint4*)(g_w + (size_t)i * 8) = u;
}

// ================= proj: 64x128 tile, K=1024; B 3-buf + wait1 ========
// SMEM: A stage s (0,1) at s*8192 (8KB each); B stage s (0..2) at 16384+s*16384.
__global__ __launch_bounds__(NT, 2) void proj_mma(const float* __restrict__ X,
                                                  const float* __restrict__ bias) {
    extern __shared__ __align__(16) char smem[];
    const uint32_t sb = smem_u32(smem);
    const int tid = threadIdx.x;
    const int warp = tid >> 5, lane = tid & 31;
    const int wm = (warp >> 2) * 32;  // 2 warps along M (64)
    const int wn = (warp & 3) * 32;   // 4 warps along N (128)
    const int mBase = blockIdx.y * 64;
    const int nBase = blockIdx.x * 128;

    float4 rA[4];
    auto ldgA = [&](int kt) {
#pragma unroll
        for (int i = 0; i < 2; i++) {
            int c = tid + i * NT;
            int row = c >> 3, ch = c & 7;
            const float4* p = (const float4*)(X + (size_t)(mBase + row) * 1024 + kt * 64 + ch * 8);
            rA[2 * i] = p[0];
            rA[2 * i + 1] = p[1];
        }
    };
    auto stsA = [&](int buf) {
        char* s = smem + buf * 8192;
#pragma unroll
        for (int i = 0; i < 2; i++) {
            int c = tid + i * NT;
            int row = c >> 3, ch = c & 7;
            uint4 u;
            u.x = packbf(rA[2 * i].x, rA[2 * i].y);
            u.y = packbf(rA[2 * i].z, rA[2 * i].w);
            u.z = packbf(rA[2 * i + 1].x, rA[2 * i + 1].y);
            u.w = packbf(rA[2 * i + 1].z, rA[2 * i + 1].w);
            *(uint4*)(s + row * 128 + ((ch ^ (row & 7)) << 4)) = u;
        }
    };
    auto issueB = [&](int kt, int buf) {
        const uint32_t B0 = sb + 16384 + buf * 16384;
#pragma unroll
        for (int i = 0; i < 4; i++) {
            int c = tid + i * NT;  // 1024 chunks: 128 rows x 8
            int row = c >> 3, ch = c & 7;
            cp16(B0 + row * 128 + ((ch ^ (row & 7)) << 4),
                 g_w + (size_t)(nBase + row) * 1024 + kt * 64 + ch * 8);
        }
        cp_commit();
    };

    float acc[2][4][4];
#pragma unroll
    for (int mi = 0; mi < 2; mi++)
#pragma unroll
        for (int ni = 0; ni < 4; ni++)
#pragma unroll
            for (int j = 0; j < 4; j++) acc[mi][ni][j] = 0.f;

    ldgA(0);
    stsA(0);
    issueB(0, 0);
    issueB(1, 1);
    ldgA(1);

    for (int kt = 0; kt < 16; kt++) {
        if (kt + 1 < 16) cp_wait1(); else cp_wait0();  // group kt complete
        __syncthreads();                               // ...and visible to all warps
        if (kt + 2 < 16) issueB(kt + 2, (kt + 2) % 3); // buf (kt-1)%3 freed by this sync
        const uint32_t aB = sb + (kt & 1) * 8192;
        const uint32_t bB = sb + 16384 + (kt % 3) * 16384;
#pragma unroll
        for (int ks = 0; ks < 4; ks++) {
            unsigned af[2][4], bfr[4][2];
#pragma unroll
            for (int mi = 0; mi < 2; mi++) {
                int row = wm + mi * 16 + (lane & 15);
                int kch = ks * 2 + (lane >> 4);
                ldsm_x4(af[mi], aB + row * 128 + ((kch ^ (row & 7)) << 4));
            }
#pragma unroll
            for (int h = 0; h < 2; h++) {
                unsigned q[4];
                int nr = wn + h * 16 + (lane & 7) + ((lane >> 4) << 3);
                int kch = ks * 2 + ((lane >> 3) & 1);
                ldsm_x4(q, bB + nr * 128 + ((kch ^ (nr & 7)) << 4));
                bfr[2 * h][0] = q[0]; bfr[2 * h][1] = q[1];
                bfr[2 * h + 1][0] = q[2]; bfr[2 * h + 1][1] = q[3];
            }
#pragma unroll
            for (int mi = 0; mi < 2; mi++)
#pragma unroll
                for (int ni = 0; ni < 4; ni++) mma16816(acc[mi][ni], af[mi], bfr[ni]);
        }
        if (kt + 1 < 16) {
            stsA((kt + 1) & 1);      // safe: sync at top of kt freed A buf (kt+1)&1
            if (kt + 2 < 16) ldgA(kt + 2);
        }
    }

    // epilogue: bias + relu -> g_h bf16
#pragma unroll
    for (int mi = 0; mi < 2; mi++) {
        int r = mBase + wm + mi * 16 + (lane >> 2);
#pragma unroll
        for (int ni = 0; ni < 4; ni++) {
            int cidx = nBase + wn + ni * 8 + ((lane & 3) << 1);
            float b0 = bias[cidx], b1 = bias[cidx + 1];
            float v00 = fmaxf(acc[mi][ni][0] + b0, 0.f);
            float v01 = fmaxf(acc[mi][ni][1] + b1, 0.f);
            float v10 = fmaxf(acc[mi][ni][2] + b0, 0.f);
            float v11 = fmaxf(acc[mi][ni][3] + b1, 0.f);
            *(__nv_bfloat162*)&g_h[(size_t)r * 256 + cidx] = __floats2bfloat162_rn(v00, v01);
            *(__nv_bfloat162*)&g_h[(size_t)(r + 8) * 256 + cidx] = __floats2bfloat162_rn(v10, v11);
        }
    }
}

// ================= gram: triangle tiles (byte-identical to R9) =======
__global__ __launch_bounds__(NT, 2) void gram_mma(const float* __restrict__ clfw,
                                                  const float* __restrict__ clfb,
                                                  float* __restrict__ out) {
    extern __shared__ __align__(16) char smem[];
    const uint32_t sb = smem_u32(smem);
    const int tid = threadIdx.x;
    const int warp = tid >> 5, lane = tid & 31;
    const int wm = (warp >> 2) * 64;
    const int wn = (warp & 3) * 32;
    const int b = blockIdx.y;

    int t = blockIdx.x, ti = 0;
    while (t >= 16 - ti) { t -= 16 - ti; ti++; }
    const int tj = ti + t;
    const int mBase = ti * 128, nBase = tj * 128;
    const __nv_bfloat16* hb = g_h + (size_t)b * (2048 * 256);

    auto issue = [&](int kt, int buf) {
        const uint32_t A0 = sb + buf * 32768, B0 = A0 + 16384;
#pragma unroll
        for (int i = 0; i < 4; i++) {
            int c = tid + i * NT;
            int r = c >> 3, ch = c & 7;
            uint32_t dst = (uint32_t)(r * 128 + ((ch ^ (r & 7)) << 4));
            cp16(A0 + dst, hb + (size_t)(mBase + r) * 256 + kt * 64 + ch * 8);
            cp16(B0 + dst, hb + (size_t)(nBase + r) * 256 + kt * 64 + ch * 8);
        }
        cp_commit();
    };

    float acc[4][4][4];
#pragma unroll
    for (int mi = 0; mi < 4; mi++)
#pragma unroll
        for (int ni = 0; ni < 4; ni++)
#pragma unroll
            for (int j = 0; j < 4; j++) acc[mi][ni][j] = 0.f;

    issue(0, 0);
    issue(1, 1);

    for (int kt = 0; kt < 4; kt++) {
        if (kt < 3) cp_wait1(); else cp_wait0();
        __syncthreads();
        if (kt + 2 < 4) issue(kt + 2, (kt + 2) % 3);
        const uint32_t aB = sb + (kt % 3) * 32768, bB = aB + 16384;
#pragma unroll
        for (int ks = 0; ks < 4; ks++) {
            unsigned af[4][4], bfr[4][2];
#pragma unroll
            for (int mi = 0; mi < 4; mi++) {
                int row = wm + mi * 16 + (lane & 15);
                int kch = ks * 2 + (lane >> 4);
                ldsm_x4(af[mi], aB + row * 128 + ((kch ^ (row & 7)) << 4));
            }
#pragma unroll
            for (int h = 0; h < 2; h++) {
                unsigned q[4];
                int nr = wn + h * 16 + (lane & 7) + ((lane >> 4) << 3);
                int kch = ks * 2 + ((lane >> 3) & 1);
                ldsm_x4(q, bB + nr * 128 + ((kch ^ (nr & 7)) << 4));
                bfr[2 * h][0] = q[0]; bfr[2 * h][1] = q[1];
                bfr[2 * h + 1][0] = q[2]; bfr[2 * h + 1][1] = q[3];
            }
#pragma unroll
            for (int mi = 0; mi < 4; mi++)
#pragma unroll
                for (int ni = 0; ni < 4; ni++) mma16816(acc[mi][ni], af[mi], bfr[ni]);
        }
    }
    __syncthreads();

    const float w = clfw[0], cb = clfb[0];
    float* op = out + (size_t)b * 2048 * 2048;
    float* ct = (float*)smem;

#pragma unroll
    for (int mi = 0; mi < 4; mi++) {
        int lr = wm + mi * 16 + (lane >> 2);
#pragma unroll
        for (int ni = 0; ni < 4; ni++) {
            int lc = wn + ni * 8 + ((lane & 3) << 1);
            float v00 = fmaf(acc[mi][ni][0], w, cb);
            float v01 = fmaf(acc[mi][ni][1], w, cb);
            float v10 = fmaf(acc[mi][ni][2], w, cb);
            float v11 = fmaf(acc[mi][ni][3], w, cb);
            *(float2*)&op[(size_t)(mBase + lr) * 2048 + nBase + lc] = make_float2(v00, v01);
            *(float2*)&op[(size_t)(mBase + lr + 8) * 2048 + nBase + lc] = make_float2(v10, v11);
            if (ti != tj) {
                ct[lc * 132 + lr] = v00;
                ct[(lc + 1) * 132 + lr] = v01;
                ct[lc * 132 + lr + 8] = v10;
                ct[(lc + 1) * 132 + lr + 8] = v11;
            }
        }
    }
    if (ti != tj) {
        __syncthreads();
#pragma unroll
        for (int idx = tid; idx < 4096; idx += NT) {
            int rr = idx >> 5, cc = idx & 31;
            float4 v = *(float4*)&ct[rr * 132 + cc * 4];
            *(float4*)&op[(size_t)(nBase + rr) * 2048 + mBase + cc * 4] = v;
        }
    }
}

extern "C" void kernel_launch(void* const* d_in, const int* in_sizes, int n_in,
                              void* d_out, int out_size) {
    (void)in_sizes; (void)n_in; (void)out_size;
    const float* hidden = (const float*)d_in[0];  // [4,2048,1024]
    const float* proj_w = (const float*)d_in[1];  // [256,1024]
    const float* proj_b = (const float*)d_in[2];  // [256]
    const float* clf_w = (const float*)d_in[3];   // [1,1]
    const float* clf_b = (const float*)d_in[4];   // [1]
    float* out = (float*)d_out;                   // [4,2048,2048]

    cudaFuncSetAttribute(proj_mma, cudaFuncAttributeMaxDynamicSharedMemorySize, 65536);
    cudaFuncSetAttribute(gram_mma, cudaFuncAttributeMaxDynamicSharedMemorySize, 98304);

    cvt_w<<<128, NT>>>(proj_w);
    proj_mma<<<dim3(2, 128), NT, 65536>>>(hidden, proj_b);
    gram_mma<<<dim3(136, 4), NT, 98304>>>(clf_w, clf_b, out);
}